// round 13
// baseline (speedup 1.0000x reference)
#include <cuda_runtime.h>
#include <cuda_fp16.h>
#include <cstdint>

#define N_NODES 100000
#define N_EDGES 1600000
#define HID 128

// ---------------- device scratch ----------------
__device__ int g_deg[N_NODES];
__device__ int g_off[N_NODES];
__device__ int g_cur[N_NODES];
__device__ int g_bsum[128];
__device__ int g_csr[N_EDGES];
__device__ int g_e32;
__device__ __half g_agg[(size_t)N_NODES * HID];  // gather output (fp16)
__device__ __half g_xh[(size_t)N_NODES * HID];   // fp16 mirror of current x
__device__ __half g_wh[8 * 128 * 128];           // fp16 TRANSPOSED weights Wt[n][k]

__device__ __forceinline__ int edge_at(const void* ei, long long idx) {
    if (g_e32) return ((const int*)ei)[idx];
    return (int)((const long long*)ei)[idx];
}

// ---------------- init: zero degrees + edge dtype detection ----------------
__global__ void init_k(const void* __restrict__ ei) {
    int i = blockIdx.x * blockDim.x + threadIdx.x;
    if (i < N_NODES) g_deg[i] = 0;
    if (i == 0) {
        const long long* p = (const long long*)ei;
        int e32 = 0;
        for (int t = 0; t < 16; t++) {
            long long v = p[t];
            if (v < 0 || v >= N_NODES) { e32 = 1; break; }
        }
        g_e32 = e32;
    }
}

// ---------------- CSR build ----------------
__global__ void count_k(const void* __restrict__ ei) {
    int e = blockIdx.x * blockDim.x + threadIdx.x;
    if (e < N_EDGES) {
        int d = edge_at(ei, (long long)N_EDGES + e);
        if (d >= 0 && d < N_NODES) atomicAdd(&g_deg[d], 1);
    }
}
__global__ void scan1_k() {
    __shared__ int s[1024];
    int t = threadIdx.x;
    int i = blockIdx.x * 1024 + t;
    int v = (i < N_NODES) ? g_deg[i] : 0;
    s[t] = v;
    __syncthreads();
    for (int o = 1; o < 1024; o <<= 1) {
        int x = (t >= o) ? s[t - o] : 0;
        __syncthreads();
        s[t] += x;
        __syncthreads();
    }
    if (i < N_NODES) g_off[i] = s[t] - v;
    if (t == 1023) g_bsum[blockIdx.x] = s[1023];
}
__global__ void scan2_k(int nb) {
    __shared__ int s[128];
    int t = threadIdx.x;
    int v = (t < nb) ? g_bsum[t] : 0;
    s[t] = v;
    __syncthreads();
    for (int o = 1; o < 128; o <<= 1) {
        int x = (t >= o) ? s[t - o] : 0;
        __syncthreads();
        s[t] += x;
        __syncthreads();
    }
    if (t < nb) g_bsum[t] = s[t] - v;
}
__global__ void scan3_k() {
    int i = blockIdx.x * blockDim.x + threadIdx.x;
    if (i < N_NODES) {
        int o = g_off[i] + g_bsum[i >> 10];
        g_off[i] = o;
        g_cur[i] = o;
    }
}
__global__ void fill_k(const void* __restrict__ ei) {
    int e = blockIdx.x * blockDim.x + threadIdx.x;
    if (e < N_EDGES) {
        int d = edge_at(ei, (long long)N_EDGES + e);
        int s = edge_at(ei, e);
        if (d < 0 || d >= N_NODES) return;
        if (s < 0) s = 0;
        if (s >= N_NODES) s = N_NODES - 1;
        int p = atomicAdd(&g_cur[d], 1);
        if (p >= 0 && p < N_EDGES) g_csr[p] = s;
    }
}

// ---------------- prep: fp16 mirror of x0 + fp16 transposed weights ----------------
__global__ void prep_k(const float* __restrict__ x,
                       const float* __restrict__ W1, const float* __restrict__ W2) {
    int i = blockIdx.x * blockDim.x + threadIdx.x;
    if (i < N_NODES * 32) {                 // tohalf: float4 index
        float4 v = ((const float4*)x)[i];
        __half2 h0 = __floats2half2_rn(v.x, v.y);
        __half2 h1 = __floats2half2_rn(v.z, v.w);
        uint2 u;
        u.x = *(uint32_t*)&h0;
        u.y = *(uint32_t*)&h1;
        ((uint2*)g_xh)[i] = u;
    }
    if (i < 8 * 128 * 32) {                 // convw: transpose to [n][k]
        int n4 = (i & 31) * 4;
        int k  = (i >> 5) & 127;
        int m  = i >> 12;
        const float* W = (m < 4) ? (W1 + (size_t)m * 16384)
                                 : (W2 + (size_t)(m - 4) * 16384);
        float4 v = *(const float4*)(W + (size_t)k * 128 + n4);
        __half* dst = g_wh + (size_t)m * 16384;
        dst[(n4 + 0) * 128 + k] = __float2half_rn(v.x);
        dst[(n4 + 1) * 128 + k] = __float2half_rn(v.y);
        dst[(n4 + 2) * 128 + k] = __float2half_rn(v.z);
        dst[(n4 + 3) * 128 + k] = __float2half_rn(v.w);
    }
}

// ---------------- gather: cp.async-pipelined, warp per node ----------------
// Half-warp h covers edges s+2i+h; each lane streams its 16B row chunk through
// a 2-stage smem ring via cp.async (no registers held in flight), accumulates
// fp32 from its OWN deposits (no cross-lane), combines halves via shfl_xor(16).
__device__ __forceinline__ void acc8(float* a, uint4 r) {
    __half2* hp = (__half2*)&r;
    float2 f0 = __half22float2(hp[0]);
    float2 f1 = __half22float2(hp[1]);
    float2 f2 = __half22float2(hp[2]);
    float2 f3 = __half22float2(hp[3]);
    a[0] += f0.x; a[1] += f0.y; a[2] += f1.x; a[3] += f1.y;
    a[4] += f2.x; a[5] += f2.y; a[6] += f3.x; a[7] += f3.y;
}

__global__ __launch_bounds__(256) void gather_k() {
    __shared__ __align__(16) char buf[8 * 4096];   // 4KB per warp (2 stages x 8 edges)
    int w = (blockIdx.x * blockDim.x + threadIdx.x) >> 5;
    int lane = threadIdx.x & 31;
    int wid = threadIdx.x >> 5;
    if (w >= N_NODES) return;                      // warp-uniform
    int half = lane >> 4;
    int sl   = lane & 15;
    char* wbuf = buf + wid * 4096;
    uint32_t wsm = (uint32_t)__cvta_generic_to_shared(wbuf);
    uint32_t mysm = wsm + half * 256 + sl * 16;    // this lane's deposit offset
    const uint4* __restrict__ X = (const uint4*)g_xh;

    float a[8];
#pragma unroll
    for (int f = 0; f < 8; f++) a[f] = 0.f;
    {
        uint4 self = __ldg(&X[(size_t)w * 16 + sl]);
        if (half == 0) acc8(a, self);
    }

    int s = g_off[w];
    int e = s + g_deg[w];
    int nblk = (e - s) >> 3;                       // full 8-edge blocks
    int kb = s;

    if (nblk > 0) {
        // issue stage 0
#pragma unroll
        for (int i = 0; i < 4; i++) {
            int j = __ldg(&g_csr[kb + 2 * i + half]);
            const void* src = &X[(size_t)j * 16 + sl];
            asm volatile("cp.async.cg.shared.global [%0], [%1], 16;\n"
                         :: "r"(mysm + i * 512), "l"(src));
        }
        asm volatile("cp.async.commit_group;\n" ::: "memory");

        for (int b = 1; b < nblk; b++) {
            int st = (b & 1) * 2048;
#pragma unroll
            for (int i = 0; i < 4; i++) {
                int j = __ldg(&g_csr[kb + 8 + 2 * i + half]);
                const void* src = &X[(size_t)j * 16 + sl];
                asm volatile("cp.async.cg.shared.global [%0], [%1], 16;\n"
                             :: "r"(mysm + st + i * 512), "l"(src));
            }
            asm volatile("cp.async.commit_group;\n" ::: "memory");
            asm volatile("cp.async.wait_group 1;\n" ::: "memory");
            int pv = ((b - 1) & 1) * 2048;
#pragma unroll
            for (int i = 0; i < 4; i++) {
                uint4 r = *(uint4*)(wbuf + pv + i * 512 + half * 256 + sl * 16);
                acc8(a, r);
            }
            kb += 8;
        }
        asm volatile("cp.async.wait_group 0;\n" ::: "memory");
        int pv = ((nblk - 1) & 1) * 2048;
#pragma unroll
        for (int i = 0; i < 4; i++) {
            uint4 r = *(uint4*)(wbuf + pv + i * 512 + half * 256 + sl * 16);
            acc8(a, r);
        }
        kb += 8;
    }
    // tail (< 8 edges), predicated direct loads
#pragma unroll
    for (int off = 0; off < 8; off += 2) {
        int k = kb + off + half;
        if (k < e) {
            int j = __ldg(&g_csr[k]);
            uint4 r = __ldg(&X[(size_t)j * 16 + sl]);
            acc8(a, r);
        }
    }
    // combine the two half-warps
#pragma unroll
    for (int f = 0; f < 8; f++)
        a[f] += __shfl_xor_sync(0xffffffffu, a[f], 16);

    if (half == 0) {
        __half2 h0 = __floats2half2_rn(a[0], a[1]);
        __half2 h1 = __floats2half2_rn(a[2], a[3]);
        __half2 h2 = __floats2half2_rn(a[4], a[5]);
        __half2 h3 = __floats2half2_rn(a[6], a[7]);
        uint4 u;
        u.x = *(uint32_t*)&h0; u.y = *(uint32_t*)&h1;
        u.z = *(uint32_t*)&h2; u.w = *(uint32_t*)&h3;
        ((uint4*)g_agg)[(size_t)w * 16 + sl] = u;
    }
}

// ---------------- fused 2-GEMM MLP (mma.sync m16n8k16 fp16) ----------------
#define FSH 136
#define SMB_B1 0
#define SMB_B2 512
#define SMB_A  1024
#define SMB_W1 (SMB_A  + 128 * FSH * 2)
#define SMB_W2 (SMB_W1 + 128 * FSH * 2)
#define SMEM_BYTES (SMB_W2 + 128 * FSH * 2)   // 105472

__device__ __forceinline__ void mmaf16(float* d, const uint32_t* a, const uint32_t* b) {
    asm volatile(
        "mma.sync.aligned.m16n8k16.row.col.f32.f16.f16.f32 "
        "{%0,%1,%2,%3}, {%4,%5,%6,%7}, {%8,%9}, {%0,%1,%2,%3};\n"
        : "+f"(d[0]), "+f"(d[1]), "+f"(d[2]), "+f"(d[3])
        : "r"(a[0]), "r"(a[1]), "r"(a[2]), "r"(a[3]), "r"(b[0]), "r"(b[1]));
}

__global__ __launch_bounds__(256, 2)
void mlp_k(int l, const float* __restrict__ b1, const float* __restrict__ b2,
           const float* __restrict__ resid, float* __restrict__ out)
{
    const __half* __restrict__ Wt1 = g_wh + (size_t)l * 16384;
    const __half* __restrict__ Wt2 = g_wh + (size_t)(4 + l) * 16384;

    extern __shared__ char smc[];
    float*  sb1 = (float*)(smc + SMB_B1);
    float*  sb2 = (float*)(smc + SMB_B2);
    __half* sA  = (__half*)(smc + SMB_A);
    __half* sW1 = (__half*)(smc + SMB_W1);
    __half* sW2 = (__half*)(smc + SMB_W2);

    int tid = threadIdx.x, wid = tid >> 5, lane = tid & 31;
    int bm = blockIdx.x * 128;

    if (tid < 128) { sb1[tid] = b1[tid]; sb2[tid] = b2[tid]; }

    {
        const uint4* W41 = (const uint4*)Wt1;
        const uint4* W42 = (const uint4*)Wt2;
#pragma unroll
        for (int it = 0; it < 8; it++) {
            int idx = it * 256 + tid;
            int n = idx >> 4, c8 = (idx & 15) * 8;
            *(uint4*)&sW1[n * FSH + c8] = W41[idx];
            *(uint4*)&sW2[n * FSH + c8] = W42[idx];
        }
    }
    {
        const uint4* A4 = (const uint4*)g_agg;
#pragma unroll
        for (int it = 0; it < 8; it++) {
            int idx = it * 256 + tid;
            int row = idx >> 4, c8 = (idx & 15) * 8;
            uint4 v = make_uint4(0, 0, 0, 0);
            if (bm + row < N_NODES) v = A4[(size_t)(bm + row) * 16 + (c8 >> 3)];
            *(uint4*)&sA[row * FSH + c8] = v;
        }
    }
    __syncthreads();

    int m_base = (wid & 3) * 32;
    int n_base = (wid >> 2) * 64;
    int qr = lane >> 2;
    int qc = lane & 3;

    float acc[2][8][4];

#pragma unroll 1
    for (int pass = 0; pass < 2; pass++) {
        const __half* sW = (pass == 0) ? sW1 : sW2;
#pragma unroll
        for (int mt = 0; mt < 2; mt++)
#pragma unroll
            for (int nt = 0; nt < 8; nt++)
#pragma unroll
                for (int j = 0; j < 4; j++) acc[mt][nt][j] = 0.f;

#pragma unroll
        for (int ks = 0; ks < 8; ks++) {
            int k = ks * 16;
            uint32_t afr[2][4];
#pragma unroll
            for (int mt = 0; mt < 2; mt++) {
                const __half* ar = &sA[(m_base + mt * 16 + qr) * FSH + k + 2 * qc];
                afr[mt][0] = *(const uint32_t*)ar;
                afr[mt][1] = *(const uint32_t*)(ar + 8 * FSH);
                afr[mt][2] = *(const uint32_t*)(ar + 8);
                afr[mt][3] = *(const uint32_t*)(ar + 8 * FSH + 8);
            }
            uint32_t bfr[8][2];
#pragma unroll
            for (int nt = 0; nt < 8; nt++) {
                const __half* br = &sW[(n_base + nt * 8 + qr) * FSH + k + 2 * qc];
                bfr[nt][0] = *(const uint32_t*)br;
                bfr[nt][1] = *(const uint32_t*)(br + 8);
            }
#pragma unroll
            for (int mt = 0; mt < 2; mt++)
#pragma unroll
                for (int nt = 0; nt < 8; nt++)
                    mmaf16(acc[mt][nt], afr[mt], bfr[nt]);
        }

        if (pass == 0) {
            __syncthreads();
#pragma unroll
            for (int mt = 0; mt < 2; mt++) {
#pragma unroll
                for (int h2 = 0; h2 < 2; h2++) {
                    int r0 = m_base + mt * 16 + qr + h2 * 8;
#pragma unroll
                    for (int nt = 0; nt < 8; nt++) {
                        int c = n_base + nt * 8 + qc * 2;
                        float vx = fmaxf(acc[mt][nt][h2 * 2 + 0] + sb1[c], 0.f);
                        float vy = fmaxf(acc[mt][nt][h2 * 2 + 1] + sb1[c + 1], 0.f);
                        *(__half2*)&sA[r0 * FSH + c] = __floats2half2_rn(vx, vy);
                    }
                }
            }
            __syncthreads();
        }
    }

#pragma unroll
    for (int mt = 0; mt < 2; mt++) {
#pragma unroll
        for (int h2 = 0; h2 < 2; h2++) {
            int r = bm + m_base + mt * 16 + qr + h2 * 8;
            if (r >= N_NODES) continue;
#pragma unroll
            for (int nt = 0; nt < 8; nt++) {
                int c = n_base + nt * 8 + qc * 2;
                float2 rv = *(const float2*)(resid + (size_t)r * 128 + c);
                float2 o;
                o.x = rv.x + fmaxf(acc[mt][nt][h2 * 2 + 0] + sb2[c], 0.f);
                o.y = rv.y + fmaxf(acc[mt][nt][h2 * 2 + 1] + sb2[c + 1], 0.f);
                *(float2*)(out + (size_t)r * 128 + c) = o;
                *(__half2*)&g_xh[(size_t)r * 128 + c] = __floats2half2_rn(o.x, o.y);
            }
        }
    }
}

// ---------------- launch ----------------
extern "C" void kernel_launch(void* const* d_in, const int* in_sizes, int n_in,
                              void* d_out, int out_size) {
    const float* x0  = (const float*)d_in[0];
    const void*  ei  = d_in[1];
    const float* W1  = (const float*)d_in[2];
    const float* b1  = (const float*)d_in[3];
    const float* W2  = (const float*)d_in[4];
    const float* b2  = (const float*)d_in[5];
    float*       xout = (float*)d_out;

    static int smem_set = 0;
    if (!smem_set) {
        cudaFuncSetAttribute(mlp_k, cudaFuncAttributeMaxDynamicSharedMemorySize,
                             SMEM_BYTES);
        smem_set = 1;
    }

    init_k<<<(N_NODES + 255) / 256, 256>>>(ei);
    count_k<<<(N_EDGES + 255) / 256, 256>>>(ei);
    int nb = (N_NODES + 1023) / 1024;
    scan1_k<<<nb, 1024>>>();
    scan2_k<<<1, 128>>>(nb);
    scan3_k<<<(N_NODES + 255) / 256, 256>>>();
    fill_k<<<(N_EDGES + 255) / 256, 256>>>(ei);
    prep_k<<<(N_NODES * 32 + 255) / 256, 256>>>(x0, W1, W2);

    int mgrid = (N_NODES + 127) / 128;   // 782
    for (int l = 0; l < 4; l++) {
        const float* xin = (l == 0) ? x0 : xout;
        gather_k<<<(N_NODES + 7) / 8, 256>>>();
        mlp_k<<<mgrid, 256, SMEM_BYTES>>>(l, b1 + (size_t)l * HID,
                                          b2 + (size_t)l * HID, xin, xout);
    }
}

// round 14
// speedup vs baseline: 1.2620x; 1.2620x over previous
#include <cuda_runtime.h>
#include <cuda_fp16.h>
#include <cstdint>

#define N_NODES 100000
#define N_EDGES 1600000
#define HID 128

// ---------------- device scratch ----------------
__device__ int g_deg[N_NODES];
__device__ int g_off[N_NODES];
__device__ int g_cur[N_NODES];
__device__ int g_bsum[128];
__device__ int g_csr[N_EDGES];
__device__ int g_e32;
__device__ __half g_agg[(size_t)N_NODES * HID];  // gather output (fp16)
__device__ __half g_xh[(size_t)N_NODES * HID];   // fp16 mirror of current x
__device__ __half g_wh[8 * 128 * 128];           // fp16 TRANSPOSED weights Wt[n][k]

__device__ __forceinline__ int edge_at(const void* ei, long long idx) {
    if (g_e32) return ((const int*)ei)[idx];
    return (int)((const long long*)ei)[idx];
}

// ---------------- init: zero degrees + edge dtype detection ----------------
__global__ void init_k(const void* __restrict__ ei) {
    int i = blockIdx.x * blockDim.x + threadIdx.x;
    if (i < N_NODES) g_deg[i] = 0;
    if (i == 0) {
        const long long* p = (const long long*)ei;
        int e32 = 0;
        for (int t = 0; t < 16; t++) {
            long long v = p[t];
            if (v < 0 || v >= N_NODES) { e32 = 1; break; }
        }
        g_e32 = e32;
    }
}

// ---------------- CSR build ----------------
__global__ void count_k(const void* __restrict__ ei) {
    int e = blockIdx.x * blockDim.x + threadIdx.x;
    if (e < N_EDGES) {
        int d = edge_at(ei, (long long)N_EDGES + e);
        if (d >= 0 && d < N_NODES) atomicAdd(&g_deg[d], 1);
    }
}
__global__ void scan1_k() {
    __shared__ int s[1024];
    int t = threadIdx.x;
    int i = blockIdx.x * 1024 + t;
    int v = (i < N_NODES) ? g_deg[i] : 0;
    s[t] = v;
    __syncthreads();
    for (int o = 1; o < 1024; o <<= 1) {
        int x = (t >= o) ? s[t - o] : 0;
        __syncthreads();
        s[t] += x;
        __syncthreads();
    }
    if (i < N_NODES) g_off[i] = s[t] - v;
    if (t == 1023) g_bsum[blockIdx.x] = s[1023];
}
__global__ void scan2_k(int nb) {
    __shared__ int s[128];
    int t = threadIdx.x;
    int v = (t < nb) ? g_bsum[t] : 0;
    s[t] = v;
    __syncthreads();
    for (int o = 1; o < 128; o <<= 1) {
        int x = (t >= o) ? s[t - o] : 0;
        __syncthreads();
        s[t] += x;
        __syncthreads();
    }
    if (t < nb) g_bsum[t] = s[t] - v;
}
__global__ void scan3_k() {
    int i = blockIdx.x * blockDim.x + threadIdx.x;
    if (i < N_NODES) {
        int o = g_off[i] + g_bsum[i >> 10];
        g_off[i] = o;
        g_cur[i] = o;
    }
}
__global__ void fill_k(const void* __restrict__ ei) {
    int e = blockIdx.x * blockDim.x + threadIdx.x;
    if (e < N_EDGES) {
        int d = edge_at(ei, (long long)N_EDGES + e);
        int s = edge_at(ei, e);
        if (d < 0 || d >= N_NODES) return;
        if (s < 0) s = 0;
        if (s >= N_NODES) s = N_NODES - 1;
        int p = atomicAdd(&g_cur[d], 1);
        if (p >= 0 && p < N_EDGES) g_csr[p] = s;
    }
}

// ---------------- prep: fp16 mirror of x0 + fp16 transposed weights ----------------
__global__ void prep_k(const float* __restrict__ x,
                       const float* __restrict__ W1, const float* __restrict__ W2) {
    int i = blockIdx.x * blockDim.x + threadIdx.x;
    if (i < N_NODES * 32) {                 // tohalf: float4 index
        float4 v = ((const float4*)x)[i];
        __half2 h0 = __floats2half2_rn(v.x, v.y);
        __half2 h1 = __floats2half2_rn(v.z, v.w);
        uint2 u;
        u.x = *(uint32_t*)&h0;
        u.y = *(uint32_t*)&h1;
        ((uint2*)g_xh)[i] = u;
    }
    if (i < 8 * 128 * 32) {                 // convw: transpose to [n][k]
        int n4 = (i & 31) * 4;
        int k  = (i >> 5) & 127;
        int m  = i >> 12;
        const float* W = (m < 4) ? (W1 + (size_t)m * 16384)
                                 : (W2 + (size_t)(m - 4) * 16384);
        float4 v = *(const float4*)(W + (size_t)k * 128 + n4);
        __half* dst = g_wh + (size_t)m * 16384;
        dst[(n4 + 0) * 128 + k] = __float2half_rn(v.x);
        dst[(n4 + 1) * 128 + k] = __float2half_rn(v.y);
        dst[(n4 + 2) * 128 + k] = __float2half_rn(v.z);
        dst[(n4 + 3) * 128 + k] = __float2half_rn(v.w);
    }
}

// ---------------- gather: half-warp per row + index prefetch pipeline ----------------
// One warp per node. Lanes 0-15 (half 0) process edges s, s+2, ...;
// lanes 16-31 (half 1) process s+1, s+3, ... Each half-warp reads a full
// 256B fp16 row via 16 x LDG.128. Indices for block b+1 are loaded while
// block b's row loads / accumulation are in flight (hides idx L2 latency).
__device__ __forceinline__ void acc8(float* a, uint4 r) {
    __half2* hp = (__half2*)&r;
    float2 f0 = __half22float2(hp[0]);
    float2 f1 = __half22float2(hp[1]);
    float2 f2 = __half22float2(hp[2]);
    float2 f3 = __half22float2(hp[3]);
    a[0] += f0.x; a[1] += f0.y; a[2] += f1.x; a[3] += f1.y;
    a[4] += f2.x; a[5] += f2.y; a[6] += f3.x; a[7] += f3.y;
}

__global__ __launch_bounds__(256) void gather_k() {
    int w = (blockIdx.x * blockDim.x + threadIdx.x) >> 5;
    int lane = threadIdx.x & 31;
    if (w >= N_NODES) return;
    int half = lane >> 4;      // 0 or 1
    int sl   = lane & 15;      // 0..15: 16B chunk within row
    const uint4* __restrict__ X = (const uint4*)g_xh;   // 16 uint4 per row

    float a[8];
    {
        uint4 self = __ldg(&X[(size_t)w * 16 + sl]);
#pragma unroll
        for (int f = 0; f < 8; f++) a[f] = 0.f;
        if (half == 0) acc8(a, self);    // self counted once
    }

    int s = g_off[w];
    int e = s + g_deg[w];
    int kb = s;

    int jj[8];
    if (kb + 16 <= e) {
#pragma unroll
        for (int i = 0; i < 8; i++) jj[i] = __ldg(&g_csr[kb + 2 * i + half]);
    }
    while (kb + 16 <= e) {
        uint4 rr[8];
#pragma unroll
        for (int i = 0; i < 8; i++) rr[i] = __ldg(&X[(size_t)jj[i] * 16 + sl]);
        int kn = kb + 16;
        if (kn + 16 <= e) {
            // prefetch next block's indices while rows are in flight
#pragma unroll
            for (int i = 0; i < 8; i++) jj[i] = __ldg(&g_csr[kn + 2 * i + half]);
        }
#pragma unroll
        for (int i = 0; i < 8; i++) acc8(a, rr[i]);
        kb = kn;
    }
    // tail (< 16 edges), warp-uniform control with per-half predicate
#pragma unroll
    for (int off = 0; off < 16; off += 2) {
        int k = kb + off + half;
        if (k < e) {
            int j = __ldg(&g_csr[k]);
            uint4 r = __ldg(&X[(size_t)j * 16 + sl]);
            acc8(a, r);
        }
    }
    // combine the two half-warps (same features, different edges)
#pragma unroll
    for (int f = 0; f < 8; f++)
        a[f] += __shfl_xor_sync(0xffffffffu, a[f], 16);

    if (half == 0) {
        __half2 h0 = __floats2half2_rn(a[0], a[1]);
        __half2 h1 = __floats2half2_rn(a[2], a[3]);
        __half2 h2 = __floats2half2_rn(a[4], a[5]);
        __half2 h3 = __floats2half2_rn(a[6], a[7]);
        uint4 u;
        u.x = *(uint32_t*)&h0; u.y = *(uint32_t*)&h1;
        u.z = *(uint32_t*)&h2; u.w = *(uint32_t*)&h3;
        ((uint4*)g_agg)[(size_t)w * 16 + sl] = u;
    }
}

// ---------------- fused 2-GEMM MLP (mma.sync m16n8k16 fp16) ----------------
// One CTA = 128 node rows, both GEMMs; h lives in smem.
//   pass0: h = fp16(relu(sA @ W1 + b1)) -> overwrite sA
//   pass1: out = resid + relu(sA @ W2 + b2); fp32 out + fp16 mirror
#define FSH 136
#define SMB_B1 0
#define SMB_B2 512
#define SMB_A  1024
#define SMB_W1 (SMB_A  + 128 * FSH * 2)
#define SMB_W2 (SMB_W1 + 128 * FSH * 2)
#define SMEM_BYTES (SMB_W2 + 128 * FSH * 2)   // 105472

__device__ __forceinline__ void mmaf16(float* d, const uint32_t* a, const uint32_t* b) {
    asm volatile(
        "mma.sync.aligned.m16n8k16.row.col.f32.f16.f16.f32 "
        "{%0,%1,%2,%3}, {%4,%5,%6,%7}, {%8,%9}, {%0,%1,%2,%3};\n"
        : "+f"(d[0]), "+f"(d[1]), "+f"(d[2]), "+f"(d[3])
        : "r"(a[0]), "r"(a[1]), "r"(a[2]), "r"(a[3]), "r"(b[0]), "r"(b[1]));
}

__global__ __launch_bounds__(256, 2)
void mlp_k(int l, const float* __restrict__ b1, const float* __restrict__ b2,
           const float* __restrict__ resid, float* __restrict__ out)
{
    const __half* __restrict__ Wt1 = g_wh + (size_t)l * 16384;
    const __half* __restrict__ Wt2 = g_wh + (size_t)(4 + l) * 16384;

    extern __shared__ char smc[];
    float*  sb1 = (float*)(smc + SMB_B1);
    float*  sb2 = (float*)(smc + SMB_B2);
    __half* sA  = (__half*)(smc + SMB_A);
    __half* sW1 = (__half*)(smc + SMB_W1);
    __half* sW2 = (__half*)(smc + SMB_W2);

    int tid = threadIdx.x, wid = tid >> 5, lane = tid & 31;
    int bm = blockIdx.x * 128;

    if (tid < 128) { sb1[tid] = b1[tid]; sb2[tid] = b2[tid]; }

    {
        const uint4* W41 = (const uint4*)Wt1;
        const uint4* W42 = (const uint4*)Wt2;
#pragma unroll
        for (int it = 0; it < 8; it++) {
            int idx = it * 256 + tid;
            int n = idx >> 4, c8 = (idx & 15) * 8;
            *(uint4*)&sW1[n * FSH + c8] = W41[idx];
            *(uint4*)&sW2[n * FSH + c8] = W42[idx];
        }
    }
    {
        const uint4* A4 = (const uint4*)g_agg;
#pragma unroll
        for (int it = 0; it < 8; it++) {
            int idx = it * 256 + tid;
            int row = idx >> 4, c8 = (idx & 15) * 8;
            uint4 v = make_uint4(0, 0, 0, 0);
            if (bm + row < N_NODES) v = A4[(size_t)(bm + row) * 16 + (c8 >> 3)];
            *(uint4*)&sA[row * FSH + c8] = v;
        }
    }
    __syncthreads();

    int m_base = (wid & 3) * 32;
    int n_base = (wid >> 2) * 64;
    int qr = lane >> 2;
    int qc = lane & 3;

    float acc[2][8][4];

#pragma unroll 1
    for (int pass = 0; pass < 2; pass++) {
        const __half* sW = (pass == 0) ? sW1 : sW2;
#pragma unroll
        for (int mt = 0; mt < 2; mt++)
#pragma unroll
            for (int nt = 0; nt < 8; nt++)
#pragma unroll
                for (int j = 0; j < 4; j++) acc[mt][nt][j] = 0.f;

#pragma unroll
        for (int ks = 0; ks < 8; ks++) {
            int k = ks * 16;
            uint32_t afr[2][4];
#pragma unroll
            for (int mt = 0; mt < 2; mt++) {
                const __half* ar = &sA[(m_base + mt * 16 + qr) * FSH + k + 2 * qc];
                afr[mt][0] = *(const uint32_t*)ar;
                afr[mt][1] = *(const uint32_t*)(ar + 8 * FSH);
                afr[mt][2] = *(const uint32_t*)(ar + 8);
                afr[mt][3] = *(const uint32_t*)(ar + 8 * FSH + 8);
            }
            uint32_t bfr[8][2];
#pragma unroll
            for (int nt = 0; nt < 8; nt++) {
                const __half* br = &sW[(n_base + nt * 8 + qr) * FSH + k + 2 * qc];
                bfr[nt][0] = *(const uint32_t*)br;
                bfr[nt][1] = *(const uint32_t*)(br + 8);
            }
#pragma unroll
            for (int mt = 0; mt < 2; mt++)
#pragma unroll
                for (int nt = 0; nt < 8; nt++)
                    mmaf16(acc[mt][nt], afr[mt], bfr[nt]);
        }

        if (pass == 0) {
            __syncthreads();
#pragma unroll
            for (int mt = 0; mt < 2; mt++) {
#pragma unroll
                for (int h2 = 0; h2 < 2; h2++) {
                    int r0 = m_base + mt * 16 + qr + h2 * 8;
#pragma unroll
                    for (int nt = 0; nt < 8; nt++) {
                        int c = n_base + nt * 8 + qc * 2;
                        float vx = fmaxf(acc[mt][nt][h2 * 2 + 0] + sb1[c], 0.f);
                        float vy = fmaxf(acc[mt][nt][h2 * 2 + 1] + sb1[c + 1], 0.f);
                        *(__half2*)&sA[r0 * FSH + c] = __floats2half2_rn(vx, vy);
                    }
                }
            }
            __syncthreads();
        }
    }

#pragma unroll
    for (int mt = 0; mt < 2; mt++) {
#pragma unroll
        for (int h2 = 0; h2 < 2; h2++) {
            int r = bm + m_base + mt * 16 + qr + h2 * 8;
            if (r >= N_NODES) continue;
#pragma unroll
            for (int nt = 0; nt < 8; nt++) {
                int c = n_base + nt * 8 + qc * 2;
                float2 rv = *(const float2*)(resid + (size_t)r * 128 + c);
                float2 o;
                o.x = rv.x + fmaxf(acc[mt][nt][h2 * 2 + 0] + sb2[c], 0.f);
                o.y = rv.y + fmaxf(acc[mt][nt][h2 * 2 + 1] + sb2[c + 1], 0.f);
                *(float2*)(out + (size_t)r * 128 + c) = o;
                *(__half2*)&g_xh[(size_t)r * 128 + c] = __floats2half2_rn(o.x, o.y);
            }
        }
    }
}

// ---------------- launch ----------------
extern "C" void kernel_launch(void* const* d_in, const int* in_sizes, int n_in,
                              void* d_out, int out_size) {
    const float* x0  = (const float*)d_in[0];
    const void*  ei  = d_in[1];
    const float* W1  = (const float*)d_in[2];
    const float* b1  = (const float*)d_in[3];
    const float* W2  = (const float*)d_in[4];
    const float* b2  = (const float*)d_in[5];
    float*       xout = (float*)d_out;

    static int smem_set = 0;
    if (!smem_set) {
        cudaFuncSetAttribute(mlp_k, cudaFuncAttributeMaxDynamicSharedMemorySize,
                             SMEM_BYTES);
        smem_set = 1;
    }

    init_k<<<(N_NODES + 255) / 256, 256>>>(ei);
    count_k<<<(N_EDGES + 255) / 256, 256>>>(ei);
    int nb = (N_NODES + 1023) / 1024;
    scan1_k<<<nb, 1024>>>();
    scan2_k<<<1, 128>>>(nb);
    scan3_k<<<(N_NODES + 255) / 256, 256>>>();
    fill_k<<<(N_EDGES + 255) / 256, 256>>>(ei);
    prep_k<<<(N_NODES * 32 + 255) / 256, 256>>>(x0, W1, W2);

    int mgrid = (N_NODES + 127) / 128;   // 782
    for (int l = 0; l < 4; l++) {
        const float* xin = (l == 0) ? x0 : xout;
        gather_k<<<(N_NODES + 7) / 8, 256>>>();
        mlp_k<<<mgrid, 256, SMEM_BYTES>>>(l, b1 + (size_t)l * HID,
                                          b2 + (size_t)l * HID, xin, xout);
    }
}

// round 16
// speedup vs baseline: 1.4765x; 1.1699x over previous
#include <cuda_runtime.h>
#include <cuda_fp16.h>
#include <cstdint>

#define N_NODES 100000
#define N_EDGES 1600000
#define HID 128

// ---------------- device scratch ----------------
__device__ int g_deg[N_NODES];
__device__ int g_off[N_NODES];
__device__ int g_cur[N_NODES];
__device__ int g_bsum[128];
__device__ int g_csr[N_EDGES];
__device__ int g_e32;
__device__ __half g_agg[(size_t)N_NODES * HID];  // gather output (fp16)
__device__ __half g_xh[(size_t)N_NODES * HID];   // fp16 mirror of current x
__device__ __half g_wh[8 * 128 * 128];           // fp16 TRANSPOSED weights Wt[n][k]

__device__ __forceinline__ int edge_at(const void* ei, long long idx) {
    if (g_e32) return ((const int*)ei)[idx];
    return (int)((const long long*)ei)[idx];
}

// ---------------- init: zero degrees + edge dtype detection ----------------
__global__ void init_k(const void* __restrict__ ei) {
    int i = blockIdx.x * blockDim.x + threadIdx.x;
    if (i < N_NODES) g_deg[i] = 0;
    if (i == 0) {
        const long long* p = (const long long*)ei;
        int e32 = 0;
        for (int t = 0; t < 16; t++) {
            long long v = p[t];
            if (v < 0 || v >= N_NODES) { e32 = 1; break; }
        }
        g_e32 = e32;
    }
}

// ---------------- CSR build ----------------
__global__ void count_k(const void* __restrict__ ei) {
    int e = blockIdx.x * blockDim.x + threadIdx.x;
    if (e < N_EDGES) {
        int d = edge_at(ei, (long long)N_EDGES + e);
        if (d >= 0 && d < N_NODES) atomicAdd(&g_deg[d], 1);
    }
}
__global__ void scan1_k() {
    __shared__ int s[1024];
    int t = threadIdx.x;
    int i = blockIdx.x * 1024 + t;
    int v = (i < N_NODES) ? g_deg[i] : 0;
    s[t] = v;
    __syncthreads();
    for (int o = 1; o < 1024; o <<= 1) {
        int x = (t >= o) ? s[t - o] : 0;
        __syncthreads();
        s[t] += x;
        __syncthreads();
    }
    if (i < N_NODES) g_off[i] = s[t] - v;
    if (t == 1023) g_bsum[blockIdx.x] = s[1023];
}
__global__ void scan2_k(int nb) {
    __shared__ int s[128];
    int t = threadIdx.x;
    int v = (t < nb) ? g_bsum[t] : 0;
    s[t] = v;
    __syncthreads();
    for (int o = 1; o < 128; o <<= 1) {
        int x = (t >= o) ? s[t - o] : 0;
        __syncthreads();
        s[t] += x;
        __syncthreads();
    }
    if (t < nb) g_bsum[t] = s[t] - v;
}
__global__ void scan3_k() {
    int i = blockIdx.x * blockDim.x + threadIdx.x;
    if (i < N_NODES) {
        int o = g_off[i] + g_bsum[i >> 10];
        g_off[i] = o;
        g_cur[i] = o;
    }
}
__global__ void fill_k(const void* __restrict__ ei) {
    int e = blockIdx.x * blockDim.x + threadIdx.x;
    if (e < N_EDGES) {
        int d = edge_at(ei, (long long)N_EDGES + e);
        int s = edge_at(ei, e);
        if (d < 0 || d >= N_NODES) return;
        if (s < 0) s = 0;
        if (s >= N_NODES) s = N_NODES - 1;
        int p = atomicAdd(&g_cur[d], 1);
        if (p >= 0 && p < N_EDGES) g_csr[p] = s;
    }
}

// ---------------- prep: fp16 mirror of x0 + fp16 transposed weights ----------------
__global__ void prep_k(const float* __restrict__ x,
                       const float* __restrict__ W1, const float* __restrict__ W2) {
    int i = blockIdx.x * blockDim.x + threadIdx.x;
    if (i < N_NODES * 32) {                 // tohalf: float4 index
        float4 v = ((const float4*)x)[i];
        __half2 h0 = __floats2half2_rn(v.x, v.y);
        __half2 h1 = __floats2half2_rn(v.z, v.w);
        uint2 u;
        u.x = *(uint32_t*)&h0;
        u.y = *(uint32_t*)&h1;
        ((uint2*)g_xh)[i] = u;
    }
    if (i < 8 * 128 * 32) {                 // convw: transpose to [n][k]
        int n4 = (i & 31) * 4;
        int k  = (i >> 5) & 127;
        int m  = i >> 12;
        const float* W = (m < 4) ? (W1 + (size_t)m * 16384)
                                 : (W2 + (size_t)(m - 4) * 16384);
        float4 v = *(const float4*)(W + (size_t)k * 128 + n4);
        __half* dst = g_wh + (size_t)m * 16384;
        dst[(n4 + 0) * 128 + k] = __float2half_rn(v.x);
        dst[(n4 + 1) * 128 + k] = __float2half_rn(v.y);
        dst[(n4 + 2) * 128 + k] = __float2half_rn(v.z);
        dst[(n4 + 3) * 128 + k] = __float2half_rn(v.w);
    }
}

// ---------------- gather: half-warp per row (EXACT R12 structure) ----------------
// One warp per node. Lanes 0-15 (half 0) process edges s, s+2, ...;
// lanes 16-31 (half 1) process s+1, s+3, ... Each half-warp reads a full
// 256B fp16 row via 16 x LDG.128. Simple dependence-free loop: the HW
// scheduler overlaps next block's index loads with current row loads.
__device__ __forceinline__ void acc8(float* a, uint4 r) {
    __half2* hp = (__half2*)&r;
    float2 f0 = __half22float2(hp[0]);
    float2 f1 = __half22float2(hp[1]);
    float2 f2 = __half22float2(hp[2]);
    float2 f3 = __half22float2(hp[3]);
    a[0] += f0.x; a[1] += f0.y; a[2] += f1.x; a[3] += f1.y;
    a[4] += f2.x; a[5] += f2.y; a[6] += f3.x; a[7] += f3.y;
}

__global__ __launch_bounds__(256) void gather_k() {
    int w = (blockIdx.x * blockDim.x + threadIdx.x) >> 5;
    int lane = threadIdx.x & 31;
    if (w >= N_NODES) return;
    int half = lane >> 4;      // 0 or 1
    int sl   = lane & 15;      // 0..15: 16B chunk within row
    const uint4* __restrict__ X = (const uint4*)g_xh;   // 16 uint4 per row

    float a[8];
    {
        uint4 self = __ldg(&X[(size_t)w * 16 + sl]);
#pragma unroll
        for (int f = 0; f < 8; f++) a[f] = 0.f;
        if (half == 0) acc8(a, self);    // self counted once
    }

    int s = g_off[w];
    int e = s + g_deg[w];
    int kb = s;
    for (; kb + 16 <= e; kb += 16) {
        int jj[8];
#pragma unroll
        for (int i = 0; i < 8; i++) jj[i] = __ldg(&g_csr[kb + 2 * i + half]);
        uint4 rr[8];
#pragma unroll
        for (int i = 0; i < 8; i++) rr[i] = __ldg(&X[(size_t)jj[i] * 16 + sl]);
#pragma unroll
        for (int i = 0; i < 8; i++) acc8(a, rr[i]);
    }
    // tail (< 16 edges), warp-uniform control with per-half predicate
#pragma unroll
    for (int off = 0; off < 16; off += 2) {
        int k = kb + off + half;
        if (k < e) {
            int j = __ldg(&g_csr[k]);
            uint4 r = __ldg(&X[(size_t)j * 16 + sl]);
            acc8(a, r);
        }
    }
    // combine the two half-warps (same features, different edges)
#pragma unroll
    for (int f = 0; f < 8; f++)
        a[f] += __shfl_xor_sync(0xffffffffu, a[f], 16);

    if (half == 0) {
        __half2 h0 = __floats2half2_rn(a[0], a[1]);
        __half2 h1 = __floats2half2_rn(a[2], a[3]);
        __half2 h2 = __floats2half2_rn(a[4], a[5]);
        __half2 h3 = __floats2half2_rn(a[6], a[7]);
        uint4 u;
        u.x = *(uint32_t*)&h0; u.y = *(uint32_t*)&h1;
        u.z = *(uint32_t*)&h2; u.w = *(uint32_t*)&h3;
        ((uint4*)g_agg)[(size_t)w * 16 + sl] = u;
    }
}

// ---------------- fused 2-GEMM MLP (mma.sync m16n8k16 fp16) ----------------
// One CTA = 128 node rows, both GEMMs; h lives in smem.
//   pass0: h = fp16(relu(sA @ W1 + b1)) -> overwrite sA
//   pass1: out = resid + relu(sA @ W2 + b2); fp32 out + fp16 mirror
#define FSH 136
#define SMB_B1 0
#define SMB_B2 512
#define SMB_A  1024
#define SMB_W1 (SMB_A  + 128 * FSH * 2)
#define SMB_W2 (SMB_W1 + 128 * FSH * 2)
#define SMEM_BYTES (SMB_W2 + 128 * FSH * 2)   // 105472

__device__ __forceinline__ void mmaf16(float* d, const uint32_t* a, const uint32_t* b) {
    asm volatile(
        "mma.sync.aligned.m16n8k16.row.col.f32.f16.f16.f32 "
        "{%0,%1,%2,%3}, {%4,%5,%6,%7}, {%8,%9}, {%0,%1,%2,%3};\n"
        : "+f"(d[0]), "+f"(d[1]), "+f"(d[2]), "+f"(d[3])
        : "r"(a[0]), "r"(a[1]), "r"(a[2]), "r"(a[3]), "r"(b[0]), "r"(b[1]));
}

__global__ __launch_bounds__(256, 2)
void mlp_k(int l, const float* __restrict__ b1, const float* __restrict__ b2,
           const float* __restrict__ resid, float* __restrict__ out)
{
    const __half* __restrict__ Wt1 = g_wh + (size_t)l * 16384;
    const __half* __restrict__ Wt2 = g_wh + (size_t)(4 + l) * 16384;

    extern __shared__ char smc[];
    float*  sb1 = (float*)(smc + SMB_B1);
    float*  sb2 = (float*)(smc + SMB_B2);
    __half* sA  = (__half*)(smc + SMB_A);
    __half* sW1 = (__half*)(smc + SMB_W1);
    __half* sW2 = (__half*)(smc + SMB_W2);

    int tid = threadIdx.x, wid = tid >> 5, lane = tid & 31;
    int bm = blockIdx.x * 128;

    if (tid < 128) { sb1[tid] = b1[tid]; sb2[tid] = b2[tid]; }

    {
        const uint4* W41 = (const uint4*)Wt1;
        const uint4* W42 = (const uint4*)Wt2;
#pragma unroll
        for (int it = 0; it < 8; it++) {
            int idx = it * 256 + tid;
            int n = idx >> 4, c8 = (idx & 15) * 8;
            *(uint4*)&sW1[n * FSH + c8] = W41[idx];
            *(uint4*)&sW2[n * FSH + c8] = W42[idx];
        }
    }
    {
        const uint4* A4 = (const uint4*)g_agg;
#pragma unroll
        for (int it = 0; it < 8; it++) {
            int idx = it * 256 + tid;
            int row = idx >> 4, c8 = (idx & 15) * 8;
            uint4 v = make_uint4(0, 0, 0, 0);
            if (bm + row < N_NODES) v = A4[(size_t)(bm + row) * 16 + (c8 >> 3)];
            *(uint4*)&sA[row * FSH + c8] = v;
        }
    }
    __syncthreads();

    int m_base = (wid & 3) * 32;
    int n_base = (wid >> 2) * 64;
    int qr = lane >> 2;
    int qc = lane & 3;

    float acc[2][8][4];

#pragma unroll 1
    for (int pass = 0; pass < 2; pass++) {
        const __half* sW = (pass == 0) ? sW1 : sW2;
#pragma unroll
        for (int mt = 0; mt < 2; mt++)
#pragma unroll
            for (int nt = 0; nt < 8; nt++)
#pragma unroll
                for (int j = 0; j < 4; j++) acc[mt][nt][j] = 0.f;

#pragma unroll
        for (int ks = 0; ks < 8; ks++) {
            int k = ks * 16;
            uint32_t afr[2][4];
#pragma unroll
            for (int mt = 0; mt < 2; mt++) {
                const __half* ar = &sA[(m_base + mt * 16 + qr) * FSH + k + 2 * qc];
                afr[mt][0] = *(const uint32_t*)ar;
                afr[mt][1] = *(const uint32_t*)(ar + 8 * FSH);
                afr[mt][2] = *(const uint32_t*)(ar + 8);
                afr[mt][3] = *(const uint32_t*)(ar + 8 * FSH + 8);
            }
            uint32_t bfr[8][2];
#pragma unroll
            for (int nt = 0; nt < 8; nt++) {
                const __half* br = &sW[(n_base + nt * 8 + qr) * FSH + k + 2 * qc];
                bfr[nt][0] = *(const uint32_t*)br;
                bfr[nt][1] = *(const uint32_t*)(br + 8);
            }
#pragma unroll
            for (int mt = 0; mt < 2; mt++)
#pragma unroll
                for (int nt = 0; nt < 8; nt++)
                    mmaf16(acc[mt][nt], afr[mt], bfr[nt]);
        }

        if (pass == 0) {
            __syncthreads();
#pragma unroll
            for (int mt = 0; mt < 2; mt++) {
#pragma unroll
                for (int h2 = 0; h2 < 2; h2++) {
                    int r0 = m_base + mt * 16 + qr + h2 * 8;
#pragma unroll
                    for (int nt = 0; nt < 8; nt++) {
                        int c = n_base + nt * 8 + qc * 2;
                        float vx = fmaxf(acc[mt][nt][h2 * 2 + 0] + sb1[c], 0.f);
                        float vy = fmaxf(acc[mt][nt][h2 * 2 + 1] + sb1[c + 1], 0.f);
                        *(__half2*)&sA[r0 * FSH + c] = __floats2half2_rn(vx, vy);
                    }
                }
            }
            __syncthreads();
        }
    }

#pragma unroll
    for (int mt = 0; mt < 2; mt++) {
#pragma unroll
        for (int h2 = 0; h2 < 2; h2++) {
            int r = bm + m_base + mt * 16 + qr + h2 * 8;
            if (r >= N_NODES) continue;
#pragma unroll
            for (int nt = 0; nt < 8; nt++) {
                int c = n_base + nt * 8 + qc * 2;
                float2 rv = *(const float2*)(resid + (size_t)r * 128 + c);
                float2 o;
                o.x = rv.x + fmaxf(acc[mt][nt][h2 * 2 + 0] + sb2[c], 0.f);
                o.y = rv.y + fmaxf(acc[mt][nt][h2 * 2 + 1] + sb2[c + 1], 0.f);
                *(float2*)(out + (size_t)r * 128 + c) = o;
                *(__half2*)&g_xh[(size_t)r * 128 + c] = __floats2half2_rn(o.x, o.y);
            }
        }
    }
}

// ---------------- launch ----------------
extern "C" void kernel_launch(void* const* d_in, const int* in_sizes, int n_in,
                              void* d_out, int out_size) {
    const float* x0  = (const float*)d_in[0];
    const void*  ei  = d_in[1];
    const float* W1  = (const float*)d_in[2];
    const float* b1  = (const float*)d_in[3];
    const float* W2  = (const float*)d_in[4];
    const float* b2  = (const float*)d_in[5];
    float*       xout = (float*)d_out;

    static int smem_set = 0;
    if (!smem_set) {
        cudaFuncSetAttribute(mlp_k, cudaFuncAttributeMaxDynamicSharedMemorySize,
                             SMEM_BYTES);
        smem_set = 1;
    }

    init_k<<<(N_NODES + 255) / 256, 256>>>(ei);
    count_k<<<(N_EDGES + 255) / 256, 256>>>(ei);
    int nb = (N_NODES + 1023) / 1024;
    scan1_k<<<nb, 1024>>>();
    scan2_k<<<1, 128>>>(nb);
    scan3_k<<<(N_NODES + 255) / 256, 256>>>();
    fill_k<<<(N_EDGES + 255) / 256, 256>>>(ei);
    prep_k<<<(N_NODES * 32 + 255) / 256, 256>>>(x0, W1, W2);

    int mgrid = (N_NODES + 127) / 128;   // 782
    for (int l = 0; l < 4; l++) {
        const float* xin = (l == 0) ? x0 : xout;
        gather_k<<<(N_NODES + 7) / 8, 256>>>();
        mlp_k<<<mgrid, 256, SMEM_BYTES>>>(l, b1 + (size_t)l * HID,
                                          b2 + (size_t)l * HID, xin, xout);
    }
}

// round 17
// speedup vs baseline: 1.5611x; 1.0573x over previous
#include <cuda_runtime.h>
#include <cuda_fp16.h>
#include <cstdint>

#define N_NODES 100000
#define N_EDGES 1600000
#define HID 128
#define NTILES ((N_NODES + 127) / 128)   // 782
#define MLP_GRID 296                      // 2 CTAs/SM x 148 SMs

// ---------------- device scratch ----------------
__device__ int g_deg[N_NODES];
__device__ int g_off[N_NODES];
__device__ int g_cur[N_NODES];
__device__ int g_bsum[128];
__device__ int g_csr[N_EDGES];
__device__ int g_e32;
__device__ __half g_agg[(size_t)N_NODES * HID];  // gather output (fp16)
__device__ __half g_xh[(size_t)N_NODES * HID];   // fp16 current x (sole state for layers 0-2)
__device__ __half g_wh[8 * 128 * 128];           // fp16 TRANSPOSED weights Wt[n][k]

__device__ __forceinline__ int edge_at(const void* ei, long long idx) {
    if (g_e32) return ((const int*)ei)[idx];
    return (int)((const long long*)ei)[idx];
}

// ---------------- init: zero degrees + edge dtype detection ----------------
__global__ void init_k(const void* __restrict__ ei) {
    int i = blockIdx.x * blockDim.x + threadIdx.x;
    if (i < N_NODES) g_deg[i] = 0;
    if (i == 0) {
        const long long* p = (const long long*)ei;
        int e32 = 0;
        for (int t = 0; t < 16; t++) {
            long long v = p[t];
            if (v < 0 || v >= N_NODES) { e32 = 1; break; }
        }
        g_e32 = e32;
    }
}

// ---------------- CSR build ----------------
__global__ void count_k(const void* __restrict__ ei) {
    int e = blockIdx.x * blockDim.x + threadIdx.x;
    if (e < N_EDGES) {
        int d = edge_at(ei, (long long)N_EDGES + e);
        if (d >= 0 && d < N_NODES) atomicAdd(&g_deg[d], 1);
    }
}
__global__ void scan1_k() {
    __shared__ int s[1024];
    int t = threadIdx.x;
    int i = blockIdx.x * 1024 + t;
    int v = (i < N_NODES) ? g_deg[i] : 0;
    s[t] = v;
    __syncthreads();
    for (int o = 1; o < 1024; o <<= 1) {
        int x = (t >= o) ? s[t - o] : 0;
        __syncthreads();
        s[t] += x;
        __syncthreads();
    }
    if (i < N_NODES) g_off[i] = s[t] - v;
    if (t == 1023) g_bsum[blockIdx.x] = s[1023];
}
__global__ void scan2_k(int nb) {
    __shared__ int s[128];
    int t = threadIdx.x;
    int v = (t < nb) ? g_bsum[t] : 0;
    s[t] = v;
    __syncthreads();
    for (int o = 1; o < 128; o <<= 1) {
        int x = (t >= o) ? s[t - o] : 0;
        __syncthreads();
        s[t] += x;
        __syncthreads();
    }
    if (t < nb) g_bsum[t] = s[t] - v;
}
__global__ void scan3_k() {
    int i = blockIdx.x * blockDim.x + threadIdx.x;
    if (i < N_NODES) {
        int o = g_off[i] + g_bsum[i >> 10];
        g_off[i] = o;
        g_cur[i] = o;
    }
}
__global__ void fill_k(const void* __restrict__ ei) {
    int e = blockIdx.x * blockDim.x + threadIdx.x;
    if (e < N_EDGES) {
        int d = edge_at(ei, (long long)N_EDGES + e);
        int s = edge_at(ei, e);
        if (d < 0 || d >= N_NODES) return;
        if (s < 0) s = 0;
        if (s >= N_NODES) s = N_NODES - 1;
        int p = atomicAdd(&g_cur[d], 1);
        if (p >= 0 && p < N_EDGES) g_csr[p] = s;
    }
}

// ---------------- prep: fp16 mirror of x0 + fp16 transposed weights ----------------
__global__ void prep_k(const float* __restrict__ x,
                       const float* __restrict__ W1, const float* __restrict__ W2) {
    int i = blockIdx.x * blockDim.x + threadIdx.x;
    if (i < N_NODES * 32) {                 // tohalf: float4 index
        float4 v = ((const float4*)x)[i];
        __half2 h0 = __floats2half2_rn(v.x, v.y);
        __half2 h1 = __floats2half2_rn(v.z, v.w);
        uint2 u;
        u.x = *(uint32_t*)&h0;
        u.y = *(uint32_t*)&h1;
        ((uint2*)g_xh)[i] = u;
    }
    if (i < 8 * 128 * 32) {                 // convw: transpose to [n][k]
        int n4 = (i & 31) * 4;
        int k  = (i >> 5) & 127;
        int m  = i >> 12;
        const float* W = (m < 4) ? (W1 + (size_t)m * 16384)
                                 : (W2 + (size_t)(m - 4) * 16384);
        float4 v = *(const float4*)(W + (size_t)k * 128 + n4);
        __half* dst = g_wh + (size_t)m * 16384;
        dst[(n4 + 0) * 128 + k] = __float2half_rn(v.x);
        dst[(n4 + 1) * 128 + k] = __float2half_rn(v.y);
        dst[(n4 + 2) * 128 + k] = __float2half_rn(v.z);
        dst[(n4 + 3) * 128 + k] = __float2half_rn(v.w);
    }
}

// ---------------- gather: half-warp per row (R12-proven structure) ----------------
__device__ __forceinline__ void acc8(float* a, uint4 r) {
    __half2* hp = (__half2*)&r;
    float2 f0 = __half22float2(hp[0]);
    float2 f1 = __half22float2(hp[1]);
    float2 f2 = __half22float2(hp[2]);
    float2 f3 = __half22float2(hp[3]);
    a[0] += f0.x; a[1] += f0.y; a[2] += f1.x; a[3] += f1.y;
    a[4] += f2.x; a[5] += f2.y; a[6] += f3.x; a[7] += f3.y;
}

__global__ __launch_bounds__(256) void gather_k() {
    int w = (blockIdx.x * blockDim.x + threadIdx.x) >> 5;
    int lane = threadIdx.x & 31;
    if (w >= N_NODES) return;
    int half = lane >> 4;
    int sl   = lane & 15;
    const uint4* __restrict__ X = (const uint4*)g_xh;

    float a[8];
    {
        uint4 self = __ldg(&X[(size_t)w * 16 + sl]);
#pragma unroll
        for (int f = 0; f < 8; f++) a[f] = 0.f;
        if (half == 0) acc8(a, self);
    }

    int s = g_off[w];
    int e = s + g_deg[w];
    int kb = s;
    for (; kb + 16 <= e; kb += 16) {
        int jj[8];
#pragma unroll
        for (int i = 0; i < 8; i++) jj[i] = __ldg(&g_csr[kb + 2 * i + half]);
        uint4 rr[8];
#pragma unroll
        for (int i = 0; i < 8; i++) rr[i] = __ldg(&X[(size_t)jj[i] * 16 + sl]);
#pragma unroll
        for (int i = 0; i < 8; i++) acc8(a, rr[i]);
    }
#pragma unroll
    for (int off = 0; off < 16; off += 2) {
        int k = kb + off + half;
        if (k < e) {
            int j = __ldg(&g_csr[k]);
            uint4 r = __ldg(&X[(size_t)j * 16 + sl]);
            acc8(a, r);
        }
    }
#pragma unroll
    for (int f = 0; f < 8; f++)
        a[f] += __shfl_xor_sync(0xffffffffu, a[f], 16);

    if (half == 0) {
        __half2 h0 = __floats2half2_rn(a[0], a[1]);
        __half2 h1 = __floats2half2_rn(a[2], a[3]);
        __half2 h2 = __floats2half2_rn(a[4], a[5]);
        __half2 h3 = __floats2half2_rn(a[6], a[7]);
        uint4 u;
        u.x = *(uint32_t*)&h0; u.y = *(uint32_t*)&h1;
        u.z = *(uint32_t*)&h2; u.w = *(uint32_t*)&h3;
        ((uint4*)g_agg)[(size_t)w * 16 + sl] = u;
    }
}

// ---------------- weight-persistent fused 2-GEMM MLP ----------------
// Grid = MLP_GRID; each CTA loops over row-tiles with W1/W2/bias resident.
//   pass0: h = fp16(relu(sA @ W1 + b1)) -> overwrite sA
//   pass1: y  = g_xh[r] + relu(sA @ W2 + b2)        (resid from fp16 mirror)
//     layers 0-2: g_xh = fp16(y)         (no fp32 traffic at all)
//     layer 3:    out  = fp32 y          (fully covers d_out)
#define FSH 136
#define SMB_B1 0
#define SMB_B2 512
#define SMB_A  1024
#define SMB_W1 (SMB_A  + 128 * FSH * 2)
#define SMB_W2 (SMB_W1 + 128 * FSH * 2)
#define SMEM_BYTES (SMB_W2 + 128 * FSH * 2)   // 105472

__device__ __forceinline__ void mmaf16(float* d, const uint32_t* a, const uint32_t* b) {
    asm volatile(
        "mma.sync.aligned.m16n8k16.row.col.f32.f16.f16.f32 "
        "{%0,%1,%2,%3}, {%4,%5,%6,%7}, {%8,%9}, {%0,%1,%2,%3};\n"
        : "+f"(d[0]), "+f"(d[1]), "+f"(d[2]), "+f"(d[3])
        : "r"(a[0]), "r"(a[1]), "r"(a[2]), "r"(a[3]), "r"(b[0]), "r"(b[1]));
}

__global__ __launch_bounds__(256, 2)
void mlp_k(int l, const float* __restrict__ b1, const float* __restrict__ b2,
           float* __restrict__ out, int final_layer)
{
    const __half* __restrict__ Wt1 = g_wh + (size_t)l * 16384;
    const __half* __restrict__ Wt2 = g_wh + (size_t)(4 + l) * 16384;

    extern __shared__ char smc[];
    float*  sb1 = (float*)(smc + SMB_B1);
    float*  sb2 = (float*)(smc + SMB_B2);
    __half* sA  = (__half*)(smc + SMB_A);
    __half* sW1 = (__half*)(smc + SMB_W1);
    __half* sW2 = (__half*)(smc + SMB_W2);

    int tid = threadIdx.x, wid = tid >> 5, lane = tid & 31;

    if (tid < 128) { sb1[tid] = b1[tid]; sb2[tid] = b2[tid]; }
    // ---- weights resident for all tiles ----
    {
        const uint4* W41 = (const uint4*)Wt1;
        const uint4* W42 = (const uint4*)Wt2;
#pragma unroll
        for (int it = 0; it < 8; it++) {
            int idx = it * 256 + tid;
            int n = idx >> 4, c8 = (idx & 15) * 8;
            *(uint4*)&sW1[n * FSH + c8] = W41[idx];
            *(uint4*)&sW2[n * FSH + c8] = W42[idx];
        }
    }

    int m_base = (wid & 3) * 32;
    int n_base = (wid >> 2) * 64;
    int qr = lane >> 2;
    int qc = lane & 3;

    for (int tile = blockIdx.x; tile < NTILES; tile += gridDim.x) {
        int bm = tile * 128;
        __syncthreads();   // weights ready (iter 0) / prior-tile sA reads done
        {
            const uint4* A4 = (const uint4*)g_agg;
#pragma unroll
            for (int it = 0; it < 8; it++) {
                int idx = it * 256 + tid;
                int row = idx >> 4, c8 = (idx & 15) * 8;
                uint4 v = make_uint4(0, 0, 0, 0);
                if (bm + row < N_NODES) v = A4[(size_t)(bm + row) * 16 + (c8 >> 3)];
                *(uint4*)&sA[row * FSH + c8] = v;
            }
        }
        __syncthreads();

        float acc[2][8][4];

#pragma unroll 1
        for (int pass = 0; pass < 2; pass++) {
            const __half* sW = (pass == 0) ? sW1 : sW2;
#pragma unroll
            for (int mt = 0; mt < 2; mt++)
#pragma unroll
                for (int nt = 0; nt < 8; nt++)
#pragma unroll
                    for (int j = 0; j < 4; j++) acc[mt][nt][j] = 0.f;

#pragma unroll
            for (int ks = 0; ks < 8; ks++) {
                int k = ks * 16;
                uint32_t afr[2][4];
#pragma unroll
                for (int mt = 0; mt < 2; mt++) {
                    const __half* ar = &sA[(m_base + mt * 16 + qr) * FSH + k + 2 * qc];
                    afr[mt][0] = *(const uint32_t*)ar;
                    afr[mt][1] = *(const uint32_t*)(ar + 8 * FSH);
                    afr[mt][2] = *(const uint32_t*)(ar + 8);
                    afr[mt][3] = *(const uint32_t*)(ar + 8 * FSH + 8);
                }
                uint32_t bfr[8][2];
#pragma unroll
                for (int nt = 0; nt < 8; nt++) {
                    const __half* br = &sW[(n_base + nt * 8 + qr) * FSH + k + 2 * qc];
                    bfr[nt][0] = *(const uint32_t*)br;
                    bfr[nt][1] = *(const uint32_t*)(br + 8);
                }
#pragma unroll
                for (int mt = 0; mt < 2; mt++)
#pragma unroll
                    for (int nt = 0; nt < 8; nt++)
                        mmaf16(acc[mt][nt], afr[mt], bfr[nt]);
            }

            if (pass == 0) {
                __syncthreads();
#pragma unroll
                for (int mt = 0; mt < 2; mt++) {
#pragma unroll
                    for (int h2 = 0; h2 < 2; h2++) {
                        int r0 = m_base + mt * 16 + qr + h2 * 8;
#pragma unroll
                        for (int nt = 0; nt < 8; nt++) {
                            int c = n_base + nt * 8 + qc * 2;
                            float vx = fmaxf(acc[mt][nt][h2 * 2 + 0] + sb1[c], 0.f);
                            float vy = fmaxf(acc[mt][nt][h2 * 2 + 1] + sb1[c + 1], 0.f);
                            *(__half2*)&sA[r0 * FSH + c] = __floats2half2_rn(vx, vy);
                        }
                    }
                }
                __syncthreads();
            }
        }

        // epilogue 2: y = g_xh[r] + relu(acc + b2)
#pragma unroll
        for (int mt = 0; mt < 2; mt++) {
#pragma unroll
            for (int h2 = 0; h2 < 2; h2++) {
                int r = bm + m_base + mt * 16 + qr + h2 * 8;
                if (r >= N_NODES) continue;
#pragma unroll
                for (int nt = 0; nt < 8; nt++) {
                    int c = n_base + nt * 8 + qc * 2;
                    __half2 rh = *(const __half2*)&g_xh[(size_t)r * 128 + c];
                    float2 rv = __half22float2(rh);
                    float ox = rv.x + fmaxf(acc[mt][nt][h2 * 2 + 0] + sb2[c], 0.f);
                    float oy = rv.y + fmaxf(acc[mt][nt][h2 * 2 + 1] + sb2[c + 1], 0.f);
                    if (final_layer) {
                        float2 o; o.x = ox; o.y = oy;
                        *(float2*)(out + (size_t)r * 128 + c) = o;
                    } else {
                        *(__half2*)&g_xh[(size_t)r * 128 + c] =
                            __floats2half2_rn(ox, oy);
                    }
                }
            }
        }
    }
}

// ---------------- launch ----------------
extern "C" void kernel_launch(void* const* d_in, const int* in_sizes, int n_in,
                              void* d_out, int out_size) {
    const float* x0  = (const float*)d_in[0];
    const void*  ei  = d_in[1];
    const float* W1  = (const float*)d_in[2];
    const float* b1  = (const float*)d_in[3];
    const float* W2  = (const float*)d_in[4];
    const float* b2  = (const float*)d_in[5];
    float*       xout = (float*)d_out;

    static int smem_set = 0;
    if (!smem_set) {
        cudaFuncSetAttribute(mlp_k, cudaFuncAttributeMaxDynamicSharedMemorySize,
                             SMEM_BYTES);
        smem_set = 1;
    }

    init_k<<<(N_NODES + 255) / 256, 256>>>(ei);
    count_k<<<(N_EDGES + 255) / 256, 256>>>(ei);
    int nb = (N_NODES + 1023) / 1024;
    scan1_k<<<nb, 1024>>>();
    scan2_k<<<1, 128>>>(nb);
    scan3_k<<<(N_NODES + 255) / 256, 256>>>();
    fill_k<<<(N_EDGES + 255) / 256, 256>>>(ei);
    prep_k<<<(N_NODES * 32 + 255) / 256, 256>>>(x0, W1, W2);

    for (int l = 0; l < 4; l++) {
        gather_k<<<(N_NODES + 7) / 8, 256>>>();
        mlp_k<<<MLP_GRID, 256, SMEM_BYTES>>>(l, b1 + (size_t)l * HID,
                                             b2 + (size_t)l * HID,
                                             xout, l == 3);
    }
}